// round 17
// baseline (speedup 1.0000x reference)
#include <cuda_runtime.h>
#include <cuda_bf16.h>
#include <cuda_fp16.h>
#include <math_constants.h>
#include <cstdint>

// ---------------------------------------------------------------------------
// ModifiedGAT: 3-layer GAT (PyG GATConv, add_self_loops=True)
//   L0: 256 -> 4x64 concat=256, ELU;  L1: 256 -> 64, ELU;  L2: 64 -> 64, ELU
// CSR-gather single-pass-softmax aggregation (fp16 h, split-head for L0) +
// split-bf16 HMMA GEMMs (ldmatrix) + single-pass scan + fused CSR fill.
// ---------------------------------------------------------------------------

#define NMAX   50000
#define EMAX   850000
#define INCH   256
#define OUTC   64

__device__ float g_h   [NMAX * 128];           // GEMM output, stored as __half (256 ch max)
__device__ float g_als [NMAX * 4];
__device__ float g_ald [NMAX * 4];
__device__ int   g_cnt [NMAX];                 // statically 0; re-zeroed by last aggr
__device__ int   g_off [NMAX + 1];
__device__ int   g_csr [EMAX];
__device__ int   g_bsum [64];
__device__ int   g_flag;                       // scan arrival counter (reset by last aggr)
__device__ __nv_bfloat16 g_ext [NMAX * 512];   // hi|lo bf16 GEMM input (stride 2*KIN)
__device__ __nv_bfloat16 g_wext[172032];       // W0 | W1 | W2 (hi|lo, [n][kext])

#define WOFF0 0
#define WOFF1 131072
#define WOFF2 163840

static inline int cdiv(int a, int b) { return (a + b - 1) / b; }

__device__ __forceinline__ uint32_t pk(__nv_bfloat16 a, __nv_bfloat16 b) {
    return (uint32_t)__bfloat16_as_ushort(a) | ((uint32_t)__bfloat16_as_ushort(b) << 16);
}
__device__ __forceinline__ void ldsm_x4(uint32_t& r0, uint32_t& r1, uint32_t& r2,
                                        uint32_t& r3, uint32_t addr) {
    asm volatile("ldmatrix.sync.aligned.m8n8.x4.shared.b16 {%0,%1,%2,%3}, [%4];"
                 : "=r"(r0), "=r"(r1), "=r"(r2), "=r"(r3) : "r"(addr));
}
__device__ __forceinline__ void ldsm_x2(uint32_t& r0, uint32_t& r1, uint32_t addr) {
    asm volatile("ldmatrix.sync.aligned.m8n8.x2.shared.b16 {%0,%1}, [%2];"
                 : "=r"(r0), "=r"(r1) : "r"(addr));
}

// ------------------- fused prep: edge count, x-ext, W-ext ------------------
__device__ __forceinline__ void wext_body(const float* __restrict__ W, int stride,
                                          int KIN, int idx, int outOff) {
    int nn   = idx & 63;
    int rest = idx >> 6;
    int kp   = rest % (KIN / 2);
    int t    = rest / (KIN / 2);
    int k0   = kp * 2;
    int col  = t * 64 + nn;
    float w0 = W[(size_t)k0 * stride + col];
    float w1 = W[(size_t)(k0 + 1) * stride + col];
    __nv_bfloat16 h0 = __float2bfloat16_rn(w0);
    __nv_bfloat16 h1 = __float2bfloat16_rn(w1);
    __nv_bfloat16 l0 = __float2bfloat16_rn(w0 - __bfloat162float(h0));
    __nv_bfloat16 l1 = __float2bfloat16_rn(w1 - __bfloat162float(h1));
    __nv_bfloat16* base = g_wext + outOff + ((size_t)t * 64 + nn) * (2 * KIN);
    *(uint32_t*)(base + k0)       = pk(h0, h1);
    *(uint32_t*)(base + KIN + k0) = pk(l0, l1);
}

__global__ void prep_k(const float* __restrict__ x, const int* __restrict__ ei,
                       const float* __restrict__ W0, const float* __restrict__ W1,
                       const float* __restrict__ W2, int n, int E, int Etot) {
    int i = blockIdx.x * blockDim.x + threadIdx.x;
    if (i < Etot) {                            // CSR degree count (g_cnt starts 0)
        int d = (i < E) ? ei[E + i] : (i - E);
        atomicAdd(&g_cnt[d], 1);
        return;
    }
    int j = i - Etot;
    const int extN = n * 64;                   // KIN=256 -> 64 float4 per row
    if (j < extN) {
        int row = j >> 6, q = j & 63;
        float4 v = ((const float4*)x)[j];
        __nv_bfloat16 h0 = __float2bfloat16_rn(v.x), h1 = __float2bfloat16_rn(v.y);
        __nv_bfloat16 h2 = __float2bfloat16_rn(v.z), h3 = __float2bfloat16_rn(v.w);
        __nv_bfloat16 l0 = __float2bfloat16_rn(v.x - __bfloat162float(h0));
        __nv_bfloat16 l1 = __float2bfloat16_rn(v.y - __bfloat162float(h1));
        __nv_bfloat16 l2 = __float2bfloat16_rn(v.z - __bfloat162float(h2));
        __nv_bfloat16 l3 = __float2bfloat16_rn(v.w - __bfloat162float(h3));
        __nv_bfloat16* d = g_ext + (size_t)row * 512 + 4 * q;
        *(uint2*)d         = make_uint2(pk(h0, h1), pk(h2, h3));
        *(uint2*)(d + 256) = make_uint2(pk(l0, l1), pk(l2, l3));
        return;
    }
    j -= extN;
    if (j < 32768) { wext_body(W0, 256, 256, j, WOFF0); return; }
    j -= 32768;
    if (j < 8192)  { wext_body(W1, 64, 256, j, WOFF1); return; }
    j -= 8192;
    if (j < 2048)  { wext_body(W2, 64, 64, j, WOFF2); return; }
}

// --------------------- single-pass CSR scan (49 blocks) --------------------
// All blocks co-resident (49 << 148 SMs): local scan, publish block sum,
// spin on arrival counter, add prefix of block sums. Deterministic.
__global__ void scan_k(int n, int Etot) {
    __shared__ int sh[32];
    __shared__ int base_sh;
    const int t = threadIdx.x, lane = t & 31, w = t >> 5;
    const int bid = blockIdx.x;
    int i = bid * 1024 + t;
    int v = (i < n) ? g_cnt[i] : 0;
    int x = v;
#pragma unroll
    for (int o = 1; o < 32; o <<= 1) {
        int y = __shfl_up_sync(0xffffffffu, x, o);
        if (lane >= o) x += y;
    }
    if (lane == 31) sh[w] = x;
    __syncthreads();
    if (w == 0) {
        int y = sh[lane];
#pragma unroll
        for (int o = 1; o < 32; o <<= 1) {
            int z = __shfl_up_sync(0xffffffffu, y, o);
            if (lane >= o) y += z;
        }
        sh[lane] = y;
    }
    __syncthreads();
    int incl = x + ((w == 0) ? 0 : sh[w - 1]);
    int excl = incl - v;
    if (t == 1023) {
        g_bsum[bid] = incl;                    // block total
        __threadfence();
        atomicAdd(&g_flag, 1);
    }
    if (t == 0) {
        while (*(volatile int*)&g_flag < gridDim.x) { }
    }
    __syncthreads();
    __threadfence();
    if (w == 0) {                              // base = sum of prior block sums
        int b = 0;
        for (int k = lane; k < bid; k += 32) b += g_bsum[k];
#pragma unroll
        for (int o = 16; o; o >>= 1) b += __shfl_xor_sync(0xffffffffu, b, o);
        if (lane == 0) base_sh = b;
    }
    __syncthreads();
    if (i < n) {
        int o = base_sh + excl;
        g_off[i] = o;
        g_cnt[i] = o;                          // fill cursor
    }
    if (bid == 0 && t == 0) g_off[n] = Etot;
}

// --------------------- split-bf16 HMMA GEMM (128x64 tile) ------------------
// C[128,64] = A[128,KIN] @ W[KIN, tile*64 .. +64]; segments hi*hi+lo*hi+hi*lo.
// Output fp16; epilogue computes attention logits. DOFILL: y==0 blocks run the
// CSR fill scatter after their tile (overlaps other blocks' MMA work).
template<int KIN, int Hh, bool DOFILL>
__global__ void __launch_bounds__(256, 1)
gemm_mma_k(const float* __restrict__ a_s, const float* __restrict__ a_d,
           int nrows, int noutTot, int wOff,
           const int* __restrict__ ei, int E, int Etot, int nbx) {
    constexpr int KEXT = 2 * KIN;
    constexpr int SA   = KEXT + 8;            // padded smem stride (elems)
    extern __shared__ __align__(16) __nv_bfloat16 sm[];
    __nv_bfloat16* As = sm;                   // [128][SA]
    __nv_bfloat16* Bs = sm + 128 * SA;        // [64][SA]
    const int tid = threadIdx.x, wid = tid >> 5, lane = tid & 31;
    const int r0 = blockIdx.x * 128;
    const int tl = blockIdx.y;

    constexpr int QA = KEXT / 8;              // uint4 per row
    for (int idx = tid; idx < 128 * QA; idx += 256) {
        int row = idx / QA, q = idx - row * QA;
        uint4 v = make_uint4(0u, 0u, 0u, 0u);
        if (r0 + row < nrows)
            v = ((const uint4*)(g_ext + (size_t)(r0 + row) * KEXT))[q];
        *(uint4*)(As + row * SA + q * 8) = v;
    }
    const __nv_bfloat16* Bg = g_wext + wOff + (size_t)tl * 64 * KEXT;
    for (int idx = tid; idx < 64 * QA; idx += 256) {
        int row = idx / QA, q = idx - row * QA;
        uint4 v = ((const uint4*)(Bg + (size_t)row * KEXT))[q];
        *(uint4*)(Bs + row * SA + q * 8) = v;
    }
    __syncthreads();

    const int g  = lane >> 2, tq = lane & 3;
    const int mr = wid * 16;
    float c[8][4];
#pragma unroll
    for (int j = 0; j < 8; j++)
#pragma unroll
        for (int i = 0; i < 4; i++) c[j][i] = 0.f;

    // ldmatrix base addresses
    const int mi = lane >> 3;
    const uint32_t baseA = (uint32_t)__cvta_generic_to_shared(As)
        + ((mr + (lane & 7) + (mi & 1) * 8) * SA + (mi >> 1) * 8) * 2;
    uint32_t baseB[8];
#pragma unroll
    for (int j = 0; j < 8; j++)
        baseB[j] = (uint32_t)__cvta_generic_to_shared(Bs)
            + ((j * 8 + (lane & 7)) * SA + ((lane >> 3) & 1) * 8) * 2;

#pragma unroll
    for (int sg = 0; sg < 3; sg++) {
        const int ak0 = (sg == 1) ? KIN : 0;
        const int bk0 = (sg == 2) ? KIN : 0;
#pragma unroll 2
        for (int ks = 0; ks < KIN / 16; ks++) {
            uint32_t a0, a1, a2, a3;
            ldsm_x4(a0, a1, a2, a3, baseA + (ak0 + ks * 16) * 2);
#pragma unroll
            for (int j = 0; j < 8; j++) {
                uint32_t b0, b1;
                ldsm_x2(b0, b1, baseB[j] + (bk0 + ks * 16) * 2);
                asm volatile(
                    "mma.sync.aligned.m16n8k16.row.col.f32.bf16.bf16.f32 "
                    "{%0,%1,%2,%3}, {%4,%5,%6,%7}, {%8,%9}, {%0,%1,%2,%3};"
                    : "+f"(c[j][0]), "+f"(c[j][1]), "+f"(c[j][2]), "+f"(c[j][3])
                    : "r"(a0), "r"(a1), "r"(a2), "r"(a3), "r"(b0), "r"(b1));
            }
        }
    }

    // store fp16
    __half* g_h16 = (__half*)g_h;
    const int gr0 = r0 + mr + g, gr1 = gr0 + 8;
    if (gr0 < nrows) {
        __half* H0 = g_h16 + (size_t)gr0 * noutTot + tl * 64 + tq * 2;
#pragma unroll
        for (int j = 0; j < 8; j++)
            *(__half2*)(H0 + j * 8) = __floats2half2_rn(c[j][0], c[j][1]);
    }
    if (gr1 < nrows) {
        __half* H1 = g_h16 + (size_t)gr1 * noutTot + tl * 64 + tq * 2;
#pragma unroll
        for (int j = 0; j < 8; j++)
            *(__half2*)(H1 + j * 8) = __floats2half2_rn(c[j][2], c[j][3]);
    }

    // fused attention logits: row dot a_s / a_d for head `tl` (fp32 regs)
    float s0 = 0.f, d0 = 0.f, s1 = 0.f, d1 = 0.f;
#pragma unroll
    for (int j = 0; j < 8; j++) {
        int cc = j * 8 + tq * 2;
        float av0 = __ldg(a_s + tl * 64 + cc), av1 = __ldg(a_s + tl * 64 + cc + 1);
        float bv0 = __ldg(a_d + tl * 64 + cc), bv1 = __ldg(a_d + tl * 64 + cc + 1);
        s0 += c[j][0] * av0 + c[j][1] * av1;
        d0 += c[j][0] * bv0 + c[j][1] * bv1;
        s1 += c[j][2] * av0 + c[j][3] * av1;
        d1 += c[j][2] * bv0 + c[j][3] * bv1;
    }
#pragma unroll
    for (int o = 1; o <= 2; o <<= 1) {
        s0 += __shfl_xor_sync(0xffffffffu, s0, o);
        d0 += __shfl_xor_sync(0xffffffffu, d0, o);
        s1 += __shfl_xor_sync(0xffffffffu, s1, o);
        d1 += __shfl_xor_sync(0xffffffffu, d1, o);
    }
    if (tq == 0) {
        if (gr0 < nrows) { g_als[gr0 * Hh + tl] = s0; g_ald[gr0 * Hh + tl] = d0; }
        if (gr1 < nrows) { g_als[gr1 * Hh + tl] = s1; g_ald[gr1 * Hh + tl] = d1; }
    }

    // fused CSR fill (y==0 blocks only), overlaps other blocks' GEMM work
    if (DOFILL && blockIdx.y == 0) {
        const int stride = nbx * 256;
        for (int i = blockIdx.x * 256 + tid; i < Etot; i += stride) {
            int s, d;
            if (i < E) { s = ei[i]; d = ei[E + i]; }
            else       { s = i - E; d = s; }
            int pos = atomicAdd(&g_cnt[d], 1);
            g_csr[pos] = s;
        }
    }
}

// ------------- fused per-dst single-pass softmax aggregation ---------------
// WPD warps per dst (2 for L0 -> each warp owns 2 heads / 128 channels);
// lane owns V = HOUT/32/WPD channels; h is fp16. UN-deep unrolled gathers,
// csr prefetched one iteration ahead, exp lane-parallel on lanes j*HL+h.
// MODE 0: write hi|lo bf16 ext (next GEMM input). MODE 1: fp32 out + resets.
template<int HOUT, int Hh, int MODE, int WPD>
__global__ void aggr_k(const float* __restrict__ bias, float* __restrict__ outp, int n) {
    const int gw   = (blockIdx.x * blockDim.x + threadIdx.x) >> 5;
    const int lane = threadIdx.x & 31;
    const int dst  = gw / WPD;
    const int wh   = gw % WPD;
    if (dst >= n) return;
    const int beg = g_off[dst], end = g_off[dst + 1];
    constexpr int V  = HOUT / 32 / WPD;       // 4 (L0), 2 (L1/2)
    constexpr int HL = Hh / WPD;              // heads per warp: 2 (L0), 1
    constexpr int UN = 8 / HL;                // 4 (L0), 8
    const int chBase   = wh * (HOUT / WPD);
    const int headBase = wh * HL;
    const int hOff     = (V * lane) >> 6;     // lane's head within warp (0..HL-1)
    const __half* g_h16 = (const __half*)g_h;

    const float ald_own = g_ald[dst * Hh + headBase + ((HL == 2) ? (lane & 1) : 0)];

    float acc[V];
#pragma unroll
    for (int k = 0; k < V; k++) acc[k] = 0.f;
    float den = 0.f;

    int e = beg;
    int s[UN];
#pragma unroll
    for (int j = 0; j < UN; j++) s[j] = 0;
    if (e + UN <= end) {
#pragma unroll
        for (int j = 0; j < UN; j++) s[j] = g_csr[e + j];
    }
    while (e + UN <= end) {
        int ns[UN];
#pragma unroll
        for (int j = 0; j < UN; j++) ns[j] = 0;
        if (e + 2 * UN <= end) {
#pragma unroll
            for (int j = 0; j < UN; j++) ns[j] = g_csr[e + UN + j];
        }
        // lanes 0..7 handle (j, h): lane = j*HL + h
        float exh = 0.f;
        if (lane < UN * HL) {
            int b0 = (HL == 2) ? ((lane >> 1) & 1) : (lane & 1);
            int b1 = (HL == 2) ? ((lane >> 2) & 1) : ((lane >> 1) & 1);
            int ss;
            int t0 = b0 ? s[1] : s[0];
            int t1 = b0 ? s[3] : s[2];
            if (UN == 4) {
                ss = b1 ? t1 : t0;
            } else {
                int b2 = (lane >> 2) & 1;
                int t2 = b0 ? s[5 % UN] : s[4 % UN];
                int t3 = b0 ? s[7 % UN] : s[6 % UN];
                int u0 = b1 ? t1 : t0;
                int u1 = b1 ? t3 : t2;
                ss = b2 ? u1 : u0;
            }
            float v = g_als[ss * Hh + headBase + ((HL == 2) ? (lane & 1) : 0)] + ald_own;
            v = v > 0.f ? v : 0.2f * v;
            exh = __expf(v);
            den += exh;
        }
        if (V == 4) {
            uint2 p[UN];
#pragma unroll
            for (int j = 0; j < UN; j++)
                p[j] = *(const uint2*)(g_h16 + (size_t)s[j] * HOUT + chBase + lane * 4);
#pragma unroll
            for (int j = 0; j < UN; j++) {
                float ex = __shfl_sync(0xffffffffu, exh, j * HL + hOff);
                float2 f0 = __half22float2(*(__half2*)&p[j].x);
                float2 f1 = __half22float2(*(__half2*)&p[j].y);
                acc[0] += ex * f0.x; acc[1] += ex * f0.y;
                acc[2] += ex * f1.x; acc[3] += ex * f1.y;
            }
        } else {
            uint32_t p[UN];
#pragma unroll
            for (int j = 0; j < UN; j++)
                p[j] = *(const uint32_t*)(g_h16 + (size_t)s[j] * HOUT + chBase + lane * 2);
#pragma unroll
            for (int j = 0; j < UN; j++) {
                float ex = __shfl_sync(0xffffffffu, exh, j * HL + hOff);
                float2 f = __half22float2(*(__half2*)&p[j]);
                acc[0] += ex * f.x; acc[1] += ex * f.y;
            }
        }
        e += UN;
#pragma unroll
        for (int j = 0; j < UN; j++) s[j] = ns[j];
    }
    // tail (deg%UN edges): per-edge path on lanes 0..HL-1 (j=0 slots)
    for (; e < end; e++) {
        int ss = g_csr[e];
        float exh = 0.f;
        if (lane < HL) {
            float v = g_als[ss * Hh + headBase + lane] + ald_own;
            v = v > 0.f ? v : 0.2f * v;
            exh = __expf(v);
            den += exh;
        }
        float ex = __shfl_sync(0xffffffffu, exh, hOff);
        if (V == 4) {
            uint2 p = *(const uint2*)(g_h16 + (size_t)ss * HOUT + chBase + lane * 4);
            float2 f0 = __half22float2(*(__half2*)&p.x);
            float2 f1 = __half22float2(*(__half2*)&p.y);
            acc[0] += ex * f0.x; acc[1] += ex * f0.y;
            acc[2] += ex * f1.x; acc[3] += ex * f1.y;
        } else {
            uint32_t p = *(const uint32_t*)(g_h16 + (size_t)ss * HOUT + chBase + lane * 2);
            float2 f = __half22float2(*(__half2*)&p);
            acc[0] += ex * f.x; acc[1] += ex * f.y;
        }
    }

    // denominator: distributed over lanes j*HL + hOff (j < UN)
    float dv = 0.f;
#pragma unroll
    for (int j = 0; j < UN; j++)
        dv += __shfl_sync(0xffffffffu, den, j * HL + hOff);
    float inv = 1.f / (dv + 1e-16f);
    float r[V];
    if (V == 4) {
        float4 b = *(const float4*)(bias + chBase + lane * 4);
        r[0] = acc[0] * inv + b.x; r[1] = acc[1] * inv + b.y;
        r[2] = acc[2] * inv + b.z; r[3] = acc[3] * inv + b.w;
    } else {
        float2 b = *(const float2*)(bias + chBase + lane * 2);
        r[0] = acc[0] * inv + b.x; r[1] = acc[1] * inv + b.y;
    }
#pragma unroll
    for (int j = 0; j < V; j++) r[j] = r[j] > 0.f ? r[j] : expm1f(r[j]);

    if (MODE == 1) {
        if (V == 2)
            *(float2*)(outp + (size_t)dst * HOUT + lane * 2) = make_float2(r[0], r[1]);
        if (lane == 0 && wh == 0) {
            g_cnt[dst] = 0;                    // reset fill cursors for next replay
            if (dst == 0) g_flag = 0;          // reset scan arrival counter
        }
    } else {
        __nv_bfloat16 hi[V], lo[V];
#pragma unroll
        for (int j = 0; j < V; j++) {
            hi[j] = __float2bfloat16_rn(r[j]);
            lo[j] = __float2bfloat16_rn(r[j] - __bfloat162float(hi[j]));
        }
        __nv_bfloat16* eb = g_ext + (size_t)dst * (2 * HOUT);
        if (V == 4) {
            *(uint2*)(eb + chBase + lane * 4) = make_uint2(pk(hi[0], hi[1]), pk(hi[2], hi[3]));
            *(uint2*)(eb + HOUT + chBase + lane * 4) = make_uint2(pk(lo[0], lo[1]), pk(lo[2], lo[3]));
        } else {
            *(uint32_t*)(eb + chBase + lane * 2)        = pk(hi[0], hi[1]);
            *(uint32_t*)(eb + HOUT + chBase + lane * 2) = pk(lo[0], lo[1]);
        }
    }
}

// ---------------------------------------------------------------------------
extern "C" void kernel_launch(void* const* d_in, const int* in_sizes, int n_in,
                              void* d_out, int out_size) {
    const float* x   = (const float*)d_in[0];
    const int*   ei  = (const int*)  d_in[1];
    const float* W0  = (const float*)d_in[2];
    const float* as0 = (const float*)d_in[3];
    const float* ad0 = (const float*)d_in[4];
    const float* b0  = (const float*)d_in[5];
    const float* W1  = (const float*)d_in[6];
    const float* as1 = (const float*)d_in[7];
    const float* ad1 = (const float*)d_in[8];
    const float* b1  = (const float*)d_in[9];
    const float* W2  = (const float*)d_in[10];
    const float* as2 = (const float*)d_in[11];
    const float* ad2 = (const float*)d_in[12];
    const float* b2  = (const float*)d_in[13];
    float* out = (float*)d_out;

    const int n    = in_sizes[0] / INCH;   // 50000
    const int E    = in_sizes[1] / 2;      // 800000
    const int Etot = E + n;

    const int SM256 = (128 + 64) * (512 + 8) * 2;   // 199,680 B
    const int SM64  = (128 + 64) * (128 + 8) * 2;   //  52,224 B
    cudaFuncSetAttribute((const void*)gemm_mma_k<256, 4, true>,  cudaFuncAttributeMaxDynamicSharedMemorySize, SM256);
    cudaFuncSetAttribute((const void*)gemm_mma_k<256, 1, false>, cudaFuncAttributeMaxDynamicSharedMemorySize, SM256);
    cudaFuncSetAttribute((const void*)gemm_mma_k<64, 1, false>,  cudaFuncAttributeMaxDynamicSharedMemorySize, SM64);

    // ---- prep (count + x ext + W ext), single-pass scan ----
    const int prepTot = Etot + n * 64 + 32768 + 8192 + 2048;
    prep_k<<<cdiv(prepTot, 256), 256>>>(x, ei, W0, W1, W2, n, E, Etot);
    scan_k<<<cdiv(n, 1024), 1024>>>(n, Etot);

    const int nb = cdiv(n, 128);

    // ---- Layer 0: 256 -> 4x64 concat (GEMM + fused CSR fill) ----
    gemm_mma_k<256, 4, true><<<dim3(nb, 4), 256, SM256>>>(as0, ad0, n, 256, WOFF0, ei, E, Etot, nb);
    aggr_k<256, 4, 0, 2><<<cdiv(n * 2, 4), 128>>>(b0, out, n);

    // ---- Layer 1: 256 -> 64 ----
    gemm_mma_k<256, 1, false><<<dim3(nb, 1), 256, SM256>>>(as1, ad1, n, 64, WOFF1, ei, E, Etot, nb);
    aggr_k<64, 1, 0, 1><<<cdiv(n, 4), 128>>>(b1, out, n);

    // ---- Layer 2: 64 -> 64 ----
    gemm_mma_k<64, 1, false><<<dim3(nb, 1), 256, SM64>>>(as2, ad2, n, 64, WOFF2, ei, E, Etot, nb);
    aggr_k<64, 1, 1, 1><<<cdiv(n, 4), 128>>>(b2, out, n);
}